// round 12
// baseline (speedup 1.0000x reference)
#include <cuda_runtime.h>
#include <cuda_fp16.h>
#include <stdint.h>

#define B_  4
#define T_  2048
#define H_  1024
#define NH_ 16
#define HD_ 64
#define M_  (B_ * T_)   // 8192

#define LOG2E 1.4426950408889634f

// fp16 scratch: projected Q(pre-scaled by 0.125*log2e)/K/V, converted X and W.
__device__ __half g_Q[M_ * H_];
__device__ __half g_K[M_ * H_];
__device__ __half g_V[M_ * H_];
__device__ __half g_X16[M_ * H_];
__device__ __half g_W16[3 * H_ * H_];
__device__ float  g_ML[B_ * T_];     // mask * LOG2E

// ===========================================================================
// PTX helpers (mma.sync / ldmatrix / cp.async — harness targets plain sm_100)
// ===========================================================================
__device__ __forceinline__ void mma_f16(float d[4], const uint32_t a[4], const uint32_t b[2]) {
    asm volatile(
        "mma.sync.aligned.m16n8k16.row.col.f32.f16.f16.f32 "
        "{%0,%1,%2,%3}, {%4,%5,%6,%7}, {%8,%9}, {%0,%1,%2,%3};\n"
        : "+f"(d[0]), "+f"(d[1]), "+f"(d[2]), "+f"(d[3])
        : "r"(a[0]), "r"(a[1]), "r"(a[2]), "r"(a[3]), "r"(b[0]), "r"(b[1]));
}
__device__ __forceinline__ void ldsm4(uint32_t addr, uint32_t &r0, uint32_t &r1,
                                      uint32_t &r2, uint32_t &r3) {
    asm volatile("ldmatrix.sync.aligned.m8n8.x4.shared.b16 {%0,%1,%2,%3}, [%4];"
                 : "=r"(r0), "=r"(r1), "=r"(r2), "=r"(r3) : "r"(addr));
}
__device__ __forceinline__ void ldsm4t(uint32_t addr, uint32_t &r0, uint32_t &r1,
                                       uint32_t &r2, uint32_t &r3) {
    asm volatile("ldmatrix.sync.aligned.m8n8.x4.trans.shared.b16 {%0,%1,%2,%3}, [%4];"
                 : "=r"(r0), "=r"(r1), "=r"(r2), "=r"(r3) : "r"(addr));
}
__device__ __forceinline__ void cp16(uint32_t saddr, const void* gaddr) {
    asm volatile("cp.async.cg.shared.global [%0], [%1], 16;" :: "r"(saddr), "l"(gaddr));
}
__device__ __forceinline__ void cp4(uint32_t saddr, const void* gaddr) {
    asm volatile("cp.async.ca.shared.global [%0], [%1], 4;" :: "r"(saddr), "l"(gaddr));
}
__device__ __forceinline__ void cp_commit() {
    asm volatile("cp.async.commit_group;" ::: "memory");
}
template <int N>
__device__ __forceinline__ void cp_wait() {
    asm volatile("cp.async.wait_group %0;" :: "n"(N) : "memory");
}

// ===========================================================================
// Prep kernels
// ===========================================================================
__global__ __launch_bounds__(256) void cvtX(
    const float* __restrict__ src, __half* __restrict__ dst, int n8)
{
    int i = blockIdx.x * blockDim.x + threadIdx.x;
    if (i < n8) {
        const float4* s4 = (const float4*)src + (size_t)i * 2;
        float4 a = s4[0], b = s4[1];
        __half2 h[4] = { __floats2half2_rn(a.x, a.y), __floats2half2_rn(a.z, a.w),
                         __floats2half2_rn(b.x, b.y), __floats2half2_rn(b.z, b.w) };
        *((uint4*)dst + i) = *(uint4*)h;
    }
}
__global__ __launch_bounds__(256) void cvtW(
    const float* __restrict__ Wq, const float* __restrict__ Wk,
    const float* __restrict__ Wv)
{
    const int z = blockIdx.z;
    const float* src = (z == 0) ? Wq : (z == 1) ? Wk : Wv;
    __half* dst = g_W16 + (size_t)z * H_ * H_;
    int i = blockIdx.x * blockDim.x + threadIdx.x;
    const float4* s4 = (const float4*)src + (size_t)i * 2;
    float4 a = s4[0], b = s4[1];
    __half2 h[4] = { __floats2half2_rn(a.x, a.y), __floats2half2_rn(a.z, a.w),
                     __floats2half2_rn(b.x, b.y), __floats2half2_rn(b.z, b.w) };
    *((uint4*)dst + i) = *(uint4*)h;
}
__global__ __launch_bounds__(256) void prepMask(const float* __restrict__ m)
{
    int i = blockIdx.x * blockDim.x + threadIdx.x;
    g_ML[i] = m[i] * LOG2E;
}

// ===========================================================================
// QKV GEMM: CTA tile 256x128, 8 warps (4m x 2n), warp tile 64x64.
// K-chunks of 64, 3-stage cp.async, explicit fragment double-buffering.
// 8 LDSM feed 32 MMAs per k16 step (ratio 4.0). No reg cap (1 CTA/SM).
// ===========================================================================
#define GLD    72
#define CTM    256
#define CTN    128
#define ASTG   (CTM * GLD)                 // A halves per stage
#define BSTG   (CTN * GLD)                 // B halves per stage
#define NSTG   3
#define NCHUNK 16
#define GEMM_SMEM (NSTG * (ASTG + BSTG) * 2)   // 165888 bytes

__global__ __launch_bounds__(256) void qkv_gemm_fp16(
    const float* __restrict__ bq, const float* __restrict__ bk,
    const float* __restrict__ bv)
{
    extern __shared__ __align__(16) __half smh[];
    const uint32_t sb = (uint32_t)__cvta_generic_to_shared(smh);

    const int z = blockIdx.z;
    const __half* Wp  = g_W16 + (size_t)z * H_ * H_;
    const float* bias = (z == 0) ? bq : (z == 1) ? bk : bv;
    __half* out       = (z == 0) ? g_Q : (z == 1) ? g_K : g_V;
    const float scale = (z == 0) ? 0.125f * LOG2E : 1.0f;

    const int tid  = threadIdx.x;
    const int lane = tid & 31;
    const int wid  = tid >> 5;
    const int bm   = blockIdx.y * CTM;
    const int bn   = blockIdx.x * CTN;
    const int moff = (wid & 3) * 64;
    const int noff = (wid >> 2) * 64;
    const int g    = lane >> 2;
    const int c    = lane & 3;
    const int arow = ((lane >> 3) & 1) * 8 + (lane & 7);
    const int acol = (lane >> 4) * 8;
    const int brow = ((lane >> 4) << 3) + (lane & 7);
    const int bcol = ((lane >> 3) & 1) * 8;

    float d[4][8][4];
    #pragma unroll
    for (int mt = 0; mt < 4; mt++)
        #pragma unroll
        for (int nt = 0; nt < 8; nt++)
            #pragma unroll
            for (int e = 0; e < 4; e++) d[mt][nt][e] = 0.f;

    auto issue = [&](int kc, int s) {
        const int k0 = kc * 64;
        const uint32_t as = sb + (s * ASTG) * 2;
        const uint32_t bs = sb + (NSTG * ASTG + s * BSTG) * 2;
        #pragma unroll
        for (int i = 0; i < 8; i++) {           // A: 256 rows x 8 units
            int u = tid + 256 * i;
            int row = u >> 3, c8 = u & 7;
            cp16(as + (row * GLD + c8 * 8) * 2,
                 g_X16 + (size_t)(bm + row) * H_ + k0 + c8 * 8);
        }
        #pragma unroll
        for (int i = 0; i < 4; i++) {           // B: 128 rows x 8 units
            int u = tid + 256 * i;
            int row = u >> 3, c8 = u & 7;
            cp16(bs + (row * GLD + c8 * 8) * 2,
                 Wp + (size_t)(bn + row) * H_ + k0 + c8 * 8);
        }
        cp_commit();
    };

    issue(0, 0);
    issue(1, 1);

    uint32_t af[2][4][4], bf[2][4][4];

    for (int kc = 0; kc < NCHUNK; kc++) {
        const int s = kc % NSTG;
        if (kc == NCHUNK - 1) cp_wait<0>(); else cp_wait<1>();
        __syncthreads();
        if (kc + 2 < NCHUNK) issue(kc + 2, (kc + 2) % NSTG);

        const uint32_t ab = sb + (s * ASTG) * 2;
        const uint32_t bb = sb + (NSTG * ASTG + s * BSTG) * 2;

        // Preload fragments for kcc = 0.
        #pragma unroll
        for (int mt = 0; mt < 4; mt++)
            ldsm4(ab + ((moff + mt * 16 + arow) * GLD + acol) * 2,
                  af[0][mt][0], af[0][mt][1], af[0][mt][2], af[0][mt][3]);
        #pragma unroll
        for (int np = 0; np < 4; np++)
            ldsm4(bb + ((noff + np * 16 + brow) * GLD + bcol) * 2,
                  bf[0][np][0], bf[0][np][1], bf[0][np][2], bf[0][np][3]);

        #pragma unroll
        for (int kcc = 0; kcc < 4; kcc++) {
            const int cur = kcc & 1, nxt = cur ^ 1;
            if (kcc < 3) {
                const int kk = (kcc + 1) * 16;
                #pragma unroll
                for (int mt = 0; mt < 4; mt++)
                    ldsm4(ab + ((moff + mt * 16 + arow) * GLD + kk + acol) * 2,
                          af[nxt][mt][0], af[nxt][mt][1], af[nxt][mt][2], af[nxt][mt][3]);
                #pragma unroll
                for (int np = 0; np < 4; np++)
                    ldsm4(bb + ((noff + np * 16 + brow) * GLD + kk + bcol) * 2,
                          bf[nxt][np][0], bf[nxt][np][1], bf[nxt][np][2], bf[nxt][np][3]);
            }
            #pragma unroll
            for (int mt = 0; mt < 4; mt++)
                #pragma unroll
                for (int np = 0; np < 4; np++) {
                    uint32_t bl[2] = { bf[cur][np][0], bf[cur][np][1] };
                    uint32_t bh[2] = { bf[cur][np][2], bf[cur][np][3] };
                    mma_f16(d[mt][2 * np],     af[cur][mt], bl);
                    mma_f16(d[mt][2 * np + 1], af[cur][mt], bh);
                }
        }
    }

    #pragma unroll
    for (int mt = 0; mt < 4; mt++) {
        int row = bm + moff + mt * 16 + g;
        #pragma unroll
        for (int nt = 0; nt < 8; nt++) {
            int col = bn + noff + nt * 8 + 2 * c;
            float2 bv2 = *(const float2*)(bias + col);
            __half2 lo = __floats2half2_rn((d[mt][nt][0] + bv2.x) * scale,
                                           (d[mt][nt][1] + bv2.y) * scale);
            __half2 hi = __floats2half2_rn((d[mt][nt][2] + bv2.x) * scale,
                                           (d[mt][nt][3] + bv2.y) * scale);
            *(__half2*)(out + (size_t)row * H_ + col)       = lo;
            *(__half2*)(out + (size_t)(row + 8) * H_ + col) = hi;
        }
    }
}

// ===========================================================================
// Flash attention — byte-identical to R11 (≈154us): 64-row Q tile,
// 4 warps x 16 rows, single-barrier double-buffered cp.async, exp2 softmax.
// ===========================================================================
#define LQH 72

__global__ __launch_bounds__(128) void attn_fp16(float* __restrict__ out)
{
    __shared__ __align__(16) __half Qs[64 * LQH];
    __shared__ __align__(16) __half Ks[2][64 * LQH];
    __shared__ __align__(16) __half Vs[2][64 * LQH];
    __shared__ float Ms[2][64];

    const int tid  = threadIdx.x;
    const int lane = tid & 31;
    const int wid  = tid >> 5;
    const int qb   = (T_ / 64 - 1) - blockIdx.x;
    const int h    = blockIdx.y;
    const int b    = blockIdx.z;
    const int g    = lane >> 2;
    const int c    = lane & 3;
    const int qrow0 = qb * 64 + wid * 16 + g;

    const uint32_t qs_base = (uint32_t)__cvta_generic_to_shared(Qs);
    const uint32_t ks_base = (uint32_t)__cvta_generic_to_shared(&Ks[0][0]);
    const uint32_t vs_base = (uint32_t)__cvta_generic_to_shared(&Vs[0][0]);
    const uint32_t ms_base = (uint32_t)__cvta_generic_to_shared(&Ms[0][0]);
    const int arow = ((lane >> 3) & 1) * 8 + (lane & 7);
    const int acol = (lane >> 4) * 8;
    const int brow = ((lane >> 4) << 3) + (lane & 7);
    const int bcol = ((lane >> 3) & 1) * 8;

    const size_t hdoff = (size_t)(b * T_) * H_ + h * HD_;
    const __half* kgb = g_K + hdoff;
    const __half* vgb = g_V + hdoff;

    auto issue = [&](int kb, int buf) {
        const __half* kg = kgb + (size_t)kb * 64 * H_;
        const __half* vg = vgb + (size_t)kb * 64 * H_;
        const uint32_t koff = ks_base + buf * (64 * LQH * 2);
        const uint32_t voff = vs_base + buf * (64 * LQH * 2);
        #pragma unroll
        for (int i = 0; i < 4; i++) {
            int u = tid + 128 * i;
            int row = u >> 3, c8 = u & 7;
            cp16(koff + (row * LQH + c8 * 8) * 2, kg + (size_t)row * H_ + c8 * 8);
            cp16(voff + (row * LQH + c8 * 8) * 2, vg + (size_t)row * H_ + c8 * 8);
        }
        if (tid < 64)
            cp4(ms_base + (buf * 64 + tid) * 4, g_ML + (size_t)b * T_ + kb * 64 + tid);
        cp_commit();
    };

    const __half* qg = g_Q + hdoff + (size_t)qb * 64 * H_;
    issue(0, 0);
    #pragma unroll
    for (int i = 0; i < 4; i++) {
        int idx = tid + 128 * i;
        int row = idx >> 3, c8 = idx & 7;
        *(uint4*)&Qs[row * LQH + c8 * 8] =
            *(const uint4*)(qg + (size_t)row * H_ + c8 * 8);
    }
    __syncthreads();

    uint32_t qa[4][4];
    #pragma unroll
    for (int kc = 0; kc < 4; kc++)
        ldsm4(qs_base + ((wid * 16 + arow) * LQH + kc * 16 + acol) * 2,
              qa[kc][0], qa[kc][1], qa[kc][2], qa[kc][3]);

    float o[8][4];
    #pragma unroll
    for (int nt = 0; nt < 8; nt++)
        #pragma unroll
        for (int e = 0; e < 4; e++) o[nt][e] = 0.f;
    float m0 = -1e30f, m1 = -1e30f, l0 = 0.f, l1 = 0.f;

    for (int kb = 0; kb <= qb; kb++) {
        const int buf = kb & 1;
        cp_wait<0>();
        __syncthreads();
        if (kb < qb) issue(kb + 1, buf ^ 1);

        const uint32_t kbb = ks_base + buf * (64 * LQH * 2);
        const uint32_t vbb = vs_base + buf * (64 * LQH * 2);
        const float* MsB = Ms[buf];

        float s[8][4];
        #pragma unroll
        for (int nt = 0; nt < 8; nt++)
            #pragma unroll
            for (int e = 0; e < 4; e++) s[nt][e] = 0.f;

        #pragma unroll
        for (int kc = 0; kc < 4; kc++) {
            const int kk = kc * 16;
            #pragma unroll
            for (int np = 0; np < 4; np++) {
                uint32_t b0, b1, b2, b3;
                ldsm4(kbb + ((np * 16 + brow) * LQH + kk + bcol) * 2, b0, b1, b2, b3);
                uint32_t bl[2] = { b0, b1 }, bh[2] = { b2, b3 };
                mma_f16(s[2 * np],     qa[kc], bl);
                mma_f16(s[2 * np + 1], qa[kc], bh);
            }
        }

        float rmax0 = -1e30f, rmax1 = -1e30f;
        #pragma unroll
        for (int nt = 0; nt < 8; nt++) {
            int lc = nt * 8 + 2 * c;
            float mk0 = MsB[lc], mk1 = MsB[lc + 1];
            s[nt][0] += mk0; s[nt][1] += mk1;
            s[nt][2] += mk0; s[nt][3] += mk1;
            if (kb == qb) {
                int col = kb * 64 + lc;
                if (col     > qrow0)     s[nt][0] = -1e30f;
                if (col + 1 > qrow0)     s[nt][1] = -1e30f;
                if (col     > qrow0 + 8) s[nt][2] = -1e30f;
                if (col + 1 > qrow0 + 8) s[nt][3] = -1e30f;
            }
            rmax0 = fmaxf(rmax0, fmaxf(s[nt][0], s[nt][1]));
            rmax1 = fmaxf(rmax1, fmaxf(s[nt][2], s[nt][3]));
        }
        rmax0 = fmaxf(rmax0, __shfl_xor_sync(0xffffffffu, rmax0, 1));
        rmax0 = fmaxf(rmax0, __shfl_xor_sync(0xffffffffu, rmax0, 2));
        rmax1 = fmaxf(rmax1, __shfl_xor_sync(0xffffffffu, rmax1, 1));
        rmax1 = fmaxf(rmax1, __shfl_xor_sync(0xffffffffu, rmax1, 2));

        float mn0 = fmaxf(m0, rmax0), mn1 = fmaxf(m1, rmax1);
        float cr0 = exp2f(m0 - mn0), cr1 = exp2f(m1 - mn1);
        m0 = mn0; m1 = mn1;
        l0 *= cr0; l1 *= cr1;

        float ps0 = 0.f, ps1 = 0.f;
        uint32_t ph[8][2];
        #pragma unroll
        for (int nt = 0; nt < 8; nt++) {
            float p0 = exp2f(s[nt][0] - m0);
            float p1 = exp2f(s[nt][1] - m0);
            float p2 = exp2f(s[nt][2] - m1);
            float p3 = exp2f(s[nt][3] - m1);
            ps0 += p0 + p1; ps1 += p2 + p3;
            __half2 h01 = __floats2half2_rn(p0, p1);
            __half2 h23 = __floats2half2_rn(p2, p3);
            ph[nt][0] = *(uint32_t*)&h01;
            ph[nt][1] = *(uint32_t*)&h23;
            o[nt][0] *= cr0; o[nt][1] *= cr0;
            o[nt][2] *= cr1; o[nt][3] *= cr1;
        }
        ps0 += __shfl_xor_sync(0xffffffffu, ps0, 1);
        ps0 += __shfl_xor_sync(0xffffffffu, ps0, 2);
        ps1 += __shfl_xor_sync(0xffffffffu, ps1, 1);
        ps1 += __shfl_xor_sync(0xffffffffu, ps1, 2);
        l0 += ps0; l1 += ps1;

        #pragma unroll
        for (int jc = 0; jc < 4; jc++) {
            uint32_t a[4] = { ph[2 * jc][0], ph[2 * jc][1],
                              ph[2 * jc + 1][0], ph[2 * jc + 1][1] };
            #pragma unroll
            for (int dp = 0; dp < 4; dp++) {
                uint32_t b0, b1, b2, b3;
                ldsm4t(vbb + ((jc * 16 + arow) * LQH + dp * 16 + acol) * 2,
                       b0, b1, b2, b3);
                uint32_t bl[2] = { b0, b1 }, bh[2] = { b2, b3 };
                mma_f16(o[2 * dp],     a, bl);
                mma_f16(o[2 * dp + 1], a, bh);
            }
        }
    }

    float inv0 = 1.f / l0, inv1 = 1.f / l1;
    float* og = out + ((size_t)(b * T_) + (size_t)qb * 64 + wid * 16 + g) * H_ + h * HD_;
    #pragma unroll
    for (int nt = 0; nt < 8; nt++) {
        int lc = nt * 8 + 2 * c;
        float2 w0, w1;
        w0.x = o[nt][0] * inv0; w0.y = o[nt][1] * inv0;
        w1.x = o[nt][2] * inv1; w1.y = o[nt][3] * inv1;
        *(float2*)(og + lc)          = w0;
        *(float2*)(og + 8 * H_ + lc) = w1;
    }
}

// ===========================================================================
// Launch
// ===========================================================================
extern "C" void kernel_launch(void* const* d_in, const int* in_sizes, int n_in,
                              void* d_out, int out_size)
{
    const float* x    = (const float*)d_in[0];
    const float* mask = (const float*)d_in[1];
    const float* Wq   = (const float*)d_in[2];
    const float* bq   = (const float*)d_in[3];
    const float* Wk   = (const float*)d_in[4];
    const float* bk   = (const float*)d_in[5];
    const float* Wv   = (const float*)d_in[6];
    const float* bv   = (const float*)d_in[7];
    float* out = (float*)d_out;

    __half *X16p;
    cudaGetSymbolAddress((void**)&X16p, g_X16);

    cudaFuncSetAttribute(qkv_gemm_fp16, cudaFuncAttributeMaxDynamicSharedMemorySize,
                         GEMM_SMEM);

    cvtX<<<(M_ * H_ / 8 + 255) / 256, 256>>>(x, X16p, M_ * H_ / 8);
    dim3 wgrid(H_ * H_ / 8 / 256, 1, 3);
    cvtW<<<wgrid, 256>>>(Wq, Wk, Wv);
    prepMask<<<B_ * T_ / 256, 256>>>(mask);

    dim3 ggrid(H_ / CTN, M_ / CTM, 3);   // (8, 32, 3) = 768 blocks
    qkv_gemm_fp16<<<ggrid, 256, GEMM_SMEM>>>(bq, bk, bv);

    dim3 agrid(T_ / 64, NH_, B_);        // (32, 16, 4)
    attn_fp16<<<agrid, 128>>>(out);
}

// round 13
// speedup vs baseline: 1.0372x; 1.0372x over previous
#include <cuda_runtime.h>
#include <cuda_fp16.h>
#include <stdint.h>

#define B_  4
#define T_  2048
#define H_  1024
#define NH_ 16
#define HD_ 64
#define M_  (B_ * T_)   // 8192

#define LOG2E 1.4426950408889634f
#define ONES2 0x3C003C00u   // half2 {1,1}

// fp16 scratch: projected Q(pre-scaled by 0.125*log2e)/K/V, converted X and W.
__device__ __half g_Q[M_ * H_];
__device__ __half g_K[M_ * H_];
__device__ __half g_V[M_ * H_];
__device__ __half g_X16[M_ * H_];
__device__ __half g_W16[3 * H_ * H_];
__device__ float  g_ML[B_ * T_];     // mask * LOG2E

// ===========================================================================
// PTX helpers (mma.sync / ldmatrix / cp.async — harness targets plain sm_100)
// ===========================================================================
__device__ __forceinline__ void mma_f16(float d[4], const uint32_t a[4], const uint32_t b[2]) {
    asm volatile(
        "mma.sync.aligned.m16n8k16.row.col.f32.f16.f16.f32 "
        "{%0,%1,%2,%3}, {%4,%5,%6,%7}, {%8,%9}, {%0,%1,%2,%3};\n"
        : "+f"(d[0]), "+f"(d[1]), "+f"(d[2]), "+f"(d[3])
        : "r"(a[0]), "r"(a[1]), "r"(a[2]), "r"(a[3]), "r"(b[0]), "r"(b[1]));
}
__device__ __forceinline__ void ldsm4(uint32_t addr, uint32_t &r0, uint32_t &r1,
                                      uint32_t &r2, uint32_t &r3) {
    asm volatile("ldmatrix.sync.aligned.m8n8.x4.shared.b16 {%0,%1,%2,%3}, [%4];"
                 : "=r"(r0), "=r"(r1), "=r"(r2), "=r"(r3) : "r"(addr));
}
__device__ __forceinline__ void ldsm4t(uint32_t addr, uint32_t &r0, uint32_t &r1,
                                       uint32_t &r2, uint32_t &r3) {
    asm volatile("ldmatrix.sync.aligned.m8n8.x4.trans.shared.b16 {%0,%1,%2,%3}, [%4];"
                 : "=r"(r0), "=r"(r1), "=r"(r2), "=r"(r3) : "r"(addr));
}
__device__ __forceinline__ void cp16(uint32_t saddr, const void* gaddr) {
    asm volatile("cp.async.cg.shared.global [%0], [%1], 16;" :: "r"(saddr), "l"(gaddr));
}
__device__ __forceinline__ void cp4(uint32_t saddr, const void* gaddr) {
    asm volatile("cp.async.ca.shared.global [%0], [%1], 4;" :: "r"(saddr), "l"(gaddr));
}
__device__ __forceinline__ void cp_commit() {
    asm volatile("cp.async.commit_group;" ::: "memory");
}
template <int N>
__device__ __forceinline__ void cp_wait() {
    asm volatile("cp.async.wait_group %0;" :: "n"(N) : "memory");
}

// ===========================================================================
// Prep kernels
// ===========================================================================
__global__ __launch_bounds__(256) void cvtX(
    const float* __restrict__ src, __half* __restrict__ dst, int n8)
{
    int i = blockIdx.x * blockDim.x + threadIdx.x;
    if (i < n8) {
        const float4* s4 = (const float4*)src + (size_t)i * 2;
        float4 a = s4[0], b = s4[1];
        __half2 h[4] = { __floats2half2_rn(a.x, a.y), __floats2half2_rn(a.z, a.w),
                         __floats2half2_rn(b.x, b.y), __floats2half2_rn(b.z, b.w) };
        *((uint4*)dst + i) = *(uint4*)h;
    }
}
__global__ __launch_bounds__(256) void cvtW(
    const float* __restrict__ Wq, const float* __restrict__ Wk,
    const float* __restrict__ Wv)
{
    const int z = blockIdx.z;
    const float* src = (z == 0) ? Wq : (z == 1) ? Wk : Wv;
    __half* dst = g_W16 + (size_t)z * H_ * H_;
    int i = blockIdx.x * blockDim.x + threadIdx.x;
    const float4* s4 = (const float4*)src + (size_t)i * 2;
    float4 a = s4[0], b = s4[1];
    __half2 h[4] = { __floats2half2_rn(a.x, a.y), __floats2half2_rn(a.z, a.w),
                     __floats2half2_rn(b.x, b.y), __floats2half2_rn(b.z, b.w) };
    *((uint4*)dst + i) = *(uint4*)h;
}
__global__ __launch_bounds__(256) void prepMask(const float* __restrict__ m)
{
    int i = blockIdx.x * blockDim.x + threadIdx.x;
    g_ML[i] = m[i] * LOG2E;
}

// ===========================================================================
// QKV GEMM — R11-exact (measured 181.7us): 128x128 tiles, 8 warps (4m x 2n),
// warp 32x64, K-chunks of 64, 3-slot cp.async, single barrier per iteration.
// ===========================================================================
#define GLD    72
#define GSTG   (128 * GLD)
#define NSTG   3
#define NCHUNK 16
#define GEMM_SMEM (2 * NSTG * GSTG * 2)    // 110592 bytes

__global__ __launch_bounds__(256, 2) void qkv_gemm_fp16(
    const float* __restrict__ bq, const float* __restrict__ bk,
    const float* __restrict__ bv)
{
    extern __shared__ __align__(16) __half smh[];
    const uint32_t sb = (uint32_t)__cvta_generic_to_shared(smh);

    const int z = blockIdx.z;
    const __half* Wp  = g_W16 + (size_t)z * H_ * H_;
    const float* bias = (z == 0) ? bq : (z == 1) ? bk : bv;
    __half* out       = (z == 0) ? g_Q : (z == 1) ? g_K : g_V;
    const float scale = (z == 0) ? 0.125f * LOG2E : 1.0f;

    const int tid  = threadIdx.x;
    const int lane = tid & 31;
    const int wid  = tid >> 5;
    const int bm   = blockIdx.y * 128;
    const int bn   = blockIdx.x * 128;
    const int moff = (wid & 3) * 32;
    const int noff = (wid >> 2) * 64;
    const int g    = lane >> 2;
    const int c    = lane & 3;
    const int arow = ((lane >> 3) & 1) * 8 + (lane & 7);
    const int acol = (lane >> 4) * 8;
    const int brow = ((lane >> 4) << 3) + (lane & 7);
    const int bcol = ((lane >> 3) & 1) * 8;

    float d[2][8][4];
    #pragma unroll
    for (int mt = 0; mt < 2; mt++)
        #pragma unroll
        for (int nt = 0; nt < 8; nt++)
            #pragma unroll
            for (int e = 0; e < 4; e++) d[mt][nt][e] = 0.f;

    auto issue = [&](int kc, int s) {
        const int k0 = kc * 64;
        #pragma unroll
        for (int i = 0; i < 4; i++) {
            int u = tid + 256 * i;
            int row = u >> 3, c8 = u & 7;
            cp16(sb + (s * GSTG + row * GLD + c8 * 8) * 2,
                 g_X16 + (size_t)(bm + row) * H_ + k0 + c8 * 8);
            cp16(sb + ((NSTG + s) * GSTG + row * GLD + c8 * 8) * 2,
                 Wp + (size_t)(bn + row) * H_ + k0 + c8 * 8);
        }
        cp_commit();
    };

    issue(0, 0);
    issue(1, 1);

    for (int kc = 0; kc < NCHUNK; kc++) {
        const int s = kc % NSTG;
        if (kc == NCHUNK - 1) cp_wait<0>(); else cp_wait<1>();
        __syncthreads();
        if (kc + 2 < NCHUNK) issue(kc + 2, (kc + 2) % NSTG);

        const uint32_t ab = sb + (s * GSTG) * 2;
        const uint32_t bb = sb + ((NSTG + s) * GSTG) * 2;
        #pragma unroll
        for (int kcc = 0; kcc < 4; kcc++) {
            const int kk = kcc * 16;
            uint32_t a[2][4];
            #pragma unroll
            for (int mt = 0; mt < 2; mt++) {
                int row = moff + mt * 16 + arow;
                ldsm4(ab + (row * GLD + kk + acol) * 2,
                      a[mt][0], a[mt][1], a[mt][2], a[mt][3]);
            }
            #pragma unroll
            for (int np = 0; np < 4; np++) {
                uint32_t b0, b1, b2, b3;
                int row = noff + np * 16 + brow;
                ldsm4(bb + (row * GLD + kk + bcol) * 2, b0, b1, b2, b3);
                uint32_t bl[2] = { b0, b1 }, bh[2] = { b2, b3 };
                #pragma unroll
                for (int mt = 0; mt < 2; mt++) {
                    mma_f16(d[mt][2 * np],     a[mt], bl);
                    mma_f16(d[mt][2 * np + 1], a[mt], bh);
                }
            }
        }
    }

    #pragma unroll
    for (int mt = 0; mt < 2; mt++) {
        int row = bm + moff + mt * 16 + g;
        #pragma unroll
        for (int nt = 0; nt < 8; nt++) {
            int col = bn + noff + nt * 8 + 2 * c;
            float2 bv2 = *(const float2*)(bias + col);
            __half2 lo = __floats2half2_rn((d[mt][nt][0] + bv2.x) * scale,
                                           (d[mt][nt][1] + bv2.y) * scale);
            __half2 hi = __floats2half2_rn((d[mt][nt][2] + bv2.x) * scale,
                                           (d[mt][nt][3] + bv2.y) * scale);
            *(__half2*)(out + (size_t)row * H_ + col)       = lo;
            *(__half2*)(out + (size_t)(row + 8) * H_ + col) = hi;
        }
    }
}

// ===========================================================================
// Flash attention: Q-tile 128 rows, 256 threads, 8 warps x 16 rows (per-warp
// math identical to R11's proven kernel). K/V tiles of 64 shared by all 8
// warps (half the cp.async/L2 traffic). Row-sum l via ones-column MMA (no
// shuffles, no scalar adds). Single-barrier double-buffered pipeline.
// ===========================================================================
#define LQH 72
#define QS_H   (128 * LQH)                       // Q halves
#define KT_B   (64 * LQH * 2)                    // K or V tile bytes per buf
#define KS_OFF(buf) (QS_H * 2 + (buf) * KT_B)
#define VS_OFF(buf) (QS_H * 2 + 2 * KT_B + (buf) * KT_B)
#define MS_OFF (QS_H * 2 + 4 * KT_B)
#define ATT_SMEM (MS_OFF + 2 * 64 * 4)           // 55808 bytes

__global__ __launch_bounds__(256, 2) void attn_fp16(float* __restrict__ out)
{
    extern __shared__ __align__(16) char smc[];
    const uint32_t sb = (uint32_t)__cvta_generic_to_shared(smc);
    __half* Qs = (__half*)smc;
    float*  Ms = (float*)(smc + MS_OFF);

    const int tid  = threadIdx.x;
    const int lane = tid & 31;
    const int wid  = tid >> 5;
    const int qt   = (T_ / 128 - 1) - blockIdx.x;   // reversed: heavy first
    const int h    = blockIdx.y;
    const int b    = blockIdx.z;
    const int g    = lane >> 2;
    const int c    = lane & 3;
    const int qrow0 = qt * 128 + wid * 16 + g;

    const int arow = ((lane >> 3) & 1) * 8 + (lane & 7);
    const int acol = (lane >> 4) * 8;
    const int brow = ((lane >> 4) << 3) + (lane & 7);
    const int bcol = ((lane >> 3) & 1) * 8;

    const size_t hdoff = (size_t)(b * T_) * H_ + h * HD_;
    const __half* kgb = g_K + hdoff;
    const __half* vgb = g_V + hdoff;

    auto issue = [&](int kb, int buf) {
        const __half* kg = kgb + (size_t)kb * 64 * H_;
        const __half* vg = vgb + (size_t)kb * 64 * H_;
        const uint32_t koff = sb + KS_OFF(buf);
        const uint32_t voff = sb + VS_OFF(buf);
        #pragma unroll
        for (int i = 0; i < 2; i++) {
            int u = tid + 256 * i;
            int row = u >> 3, c8 = u & 7;
            cp16(koff + (row * LQH + c8 * 8) * 2, kg + (size_t)row * H_ + c8 * 8);
            cp16(voff + (row * LQH + c8 * 8) * 2, vg + (size_t)row * H_ + c8 * 8);
        }
        if (tid < 64)
            cp4(sb + MS_OFF + (buf * 64 + tid) * 4, g_ML + (size_t)b * T_ + kb * 64 + tid);
        cp_commit();
    };

    // Stage Q (128 rows) + prefetch k-tile 0.
    const __half* qg = g_Q + hdoff + (size_t)qt * 128 * H_;
    issue(0, 0);
    #pragma unroll
    for (int i = 0; i < 4; i++) {
        int idx = tid + 256 * i;
        int row = idx >> 3, c8 = idx & 7;
        *(uint4*)&Qs[row * LQH + c8 * 8] =
            *(const uint4*)(qg + (size_t)row * H_ + c8 * 8);
    }
    __syncthreads();

    uint32_t qa[4][4];
    #pragma unroll
    for (int kc = 0; kc < 4; kc++)
        ldsm4(sb + ((wid * 16 + arow) * LQH + kc * 16 + acol) * 2,
              qa[kc][0], qa[kc][1], qa[kc][2], qa[kc][3]);

    float o[8][4];
    #pragma unroll
    for (int nt = 0; nt < 8; nt++)
        #pragma unroll
        for (int e = 0; e < 4; e++) o[nt][e] = 0.f;
    float lacc[4] = { 0.f, 0.f, 0.f, 0.f };        // row sums via ones-MMA
    float m0 = -1e30f, m1 = -1e30f;

    const uint32_t onesb[2] = { ONES2, ONES2 };

    const int nkb = 2 * qt + 2;
    for (int kb = 0; kb < nkb; kb++) {
        const int buf = kb & 1;
        cp_wait<0>();
        __syncthreads();
        if (kb < nkb - 1) issue(kb + 1, buf ^ 1);

        const uint32_t kbb = sb + KS_OFF(buf);
        const uint32_t vbb = sb + VS_OFF(buf);
        const float* MsB = Ms + buf * 64;

        // ---- S = Q K^T ----
        float s[8][4];
        #pragma unroll
        for (int nt = 0; nt < 8; nt++)
            #pragma unroll
            for (int e = 0; e < 4; e++) s[nt][e] = 0.f;

        #pragma unroll
        for (int kc = 0; kc < 4; kc++) {
            const int kk = kc * 16;
            #pragma unroll
            for (int np = 0; np < 4; np++) {
                uint32_t b0, b1, b2, b3;
                ldsm4(kbb + ((np * 16 + brow) * LQH + kk + bcol) * 2, b0, b1, b2, b3);
                uint32_t bl[2] = { b0, b1 }, bh[2] = { b2, b3 };
                mma_f16(s[2 * np],     qa[kc], bl);
                mma_f16(s[2 * np + 1], qa[kc], bh);
            }
        }

        // ---- mask + online softmax (exp2 domain) ----
        float rmax0 = -1e30f, rmax1 = -1e30f;
        #pragma unroll
        for (int nt = 0; nt < 8; nt++) {
            int lc = nt * 8 + 2 * c;
            float mk0 = MsB[lc], mk1 = MsB[lc + 1];
            s[nt][0] += mk0; s[nt][1] += mk1;
            s[nt][2] += mk0; s[nt][3] += mk1;
            if (kb >= 2 * qt) {
                int col = kb * 64 + lc;
                if (col     > qrow0)     s[nt][0] = -1e30f;
                if (col + 1 > qrow0)     s[nt][1] = -1e30f;
                if (col     > qrow0 + 8) s[nt][2] = -1e30f;
                if (col + 1 > qrow0 + 8) s[nt][3] = -1e30f;
            }
            rmax0 = fmaxf(rmax0, fmaxf(s[nt][0], s[nt][1]));
            rmax1 = fmaxf(rmax1, fmaxf(s[nt][2], s[nt][3]));
        }
        rmax0 = fmaxf(rmax0, __shfl_xor_sync(0xffffffffu, rmax0, 1));
        rmax0 = fmaxf(rmax0, __shfl_xor_sync(0xffffffffu, rmax0, 2));
        rmax1 = fmaxf(rmax1, __shfl_xor_sync(0xffffffffu, rmax1, 1));
        rmax1 = fmaxf(rmax1, __shfl_xor_sync(0xffffffffu, rmax1, 2));

        float mn0 = fmaxf(m0, rmax0), mn1 = fmaxf(m1, rmax1);
        float cr0 = exp2f(m0 - mn0), cr1 = exp2f(m1 - mn1);
        m0 = mn0; m1 = mn1;

        uint32_t ph[8][2];
        #pragma unroll
        for (int nt = 0; nt < 8; nt++) {
            float p0 = exp2f(s[nt][0] - m0);
            float p1 = exp2f(s[nt][1] - m0);
            float p2 = exp2f(s[nt][2] - m1);
            float p3 = exp2f(s[nt][3] - m1);
            __half2 h01 = __floats2half2_rn(p0, p1);
            __half2 h23 = __floats2half2_rn(p2, p3);
            ph[nt][0] = *(uint32_t*)&h01;
            ph[nt][1] = *(uint32_t*)&h23;
            o[nt][0] *= cr0; o[nt][1] *= cr0;
            o[nt][2] *= cr1; o[nt][3] *= cr1;
        }
        lacc[0] *= cr0; lacc[2] *= cr1;

        // ---- O += P V ; l += P * ones ----
        #pragma unroll
        for (int jc = 0; jc < 4; jc++) {
            uint32_t a[4] = { ph[2 * jc][0], ph[2 * jc][1],
                              ph[2 * jc + 1][0], ph[2 * jc + 1][1] };
            mma_f16(lacc, a, onesb);   // row sums (all cols identical)
            #pragma unroll
            for (int dp = 0; dp < 4; dp++) {
                uint32_t b0, b1, b2, b3;
                ldsm4t(vbb + ((jc * 16 + arow) * LQH + dp * 16 + acol) * 2,
                       b0, b1, b2, b3);
                uint32_t bl[2] = { b0, b1 }, bh[2] = { b2, b3 };
                mma_f16(o[2 * dp],     a, bl);
                mma_f16(o[2 * dp + 1], a, bh);
            }
        }
    }

    float inv0 = 1.f / lacc[0], inv1 = 1.f / lacc[2];
    float* og = out + ((size_t)(b * T_) + (size_t)qt * 128 + wid * 16 + g) * H_ + h * HD_;
    #pragma unroll
    for (int nt = 0; nt < 8; nt++) {
        int lc = nt * 8 + 2 * c;
        float2 w0, w1;
        w0.x = o[nt][0] * inv0; w0.y = o[nt][1] * inv0;
        w1.x = o[nt][2] * inv1; w1.y = o[nt][3] * inv1;
        *(float2*)(og + lc)          = w0;
        *(float2*)(og + 8 * H_ + lc) = w1;
    }
}

// ===========================================================================
// Launch
// ===========================================================================
extern "C" void kernel_launch(void* const* d_in, const int* in_sizes, int n_in,
                              void* d_out, int out_size)
{
    const float* x    = (const float*)d_in[0];
    const float* mask = (const float*)d_in[1];
    const float* Wq   = (const float*)d_in[2];
    const float* bq   = (const float*)d_in[3];
    const float* Wk   = (const float*)d_in[4];
    const float* bk   = (const float*)d_in[5];
    const float* Wv   = (const float*)d_in[6];
    const float* bv   = (const float*)d_in[7];
    float* out = (float*)d_out;

    __half *X16p;
    cudaGetSymbolAddress((void**)&X16p, g_X16);

    cudaFuncSetAttribute(qkv_gemm_fp16, cudaFuncAttributeMaxDynamicSharedMemorySize,
                         GEMM_SMEM);
    cudaFuncSetAttribute(attn_fp16, cudaFuncAttributeMaxDynamicSharedMemorySize,
                         ATT_SMEM);

    cvtX<<<(M_ * H_ / 8 + 255) / 256, 256>>>(x, X16p, M_ * H_ / 8);
    dim3 wgrid(H_ * H_ / 8 / 256, 1, 3);
    cvtW<<<wgrid, 256>>>(Wq, Wk, Wv);
    prepMask<<<B_ * T_ / 256, 256>>>(mask);

    dim3 ggrid(H_ / 128, M_ / 128, 3);   // (8, 64, 3)
    qkv_gemm_fp16<<<ggrid, 256, GEMM_SMEM>>>(bq, bk, bv);

    dim3 agrid(T_ / 128, NH_, B_);       // (16, 16, 4)
    attn_fp16<<<agrid, 256, ATT_SMEM>>>(out);
}

// round 15
// speedup vs baseline: 1.0946x; 1.0553x over previous
#include <cuda_runtime.h>
#include <cuda_fp16.h>
#include <stdint.h>

#define B_  4
#define T_  2048
#define H_  1024
#define NH_ 16
#define HD_ 64
#define M_  (B_ * T_)   // 8192

#define LOG2E 1.4426950408889634f
#define ONES2 0x3C003C00u   // half2 {1,1}

// fp16 scratch: projected Q(pre-scaled by 0.125*log2e)/K/V, converted X and W.
__device__ __half g_Q[M_ * H_];
__device__ __half g_K[M_ * H_];
__device__ __half g_V[M_ * H_];
__device__ __half g_X16[M_ * H_];
__device__ __half g_W16[3 * H_ * H_];
__device__ float  g_ML[B_ * T_];     // mask * LOG2E

// ===========================================================================
// PTX helpers (mma.sync / ldmatrix / cp.async — harness targets plain sm_100)
// ===========================================================================
__device__ __forceinline__ void mma_f16(float d[4], const uint32_t a[4], const uint32_t b[2]) {
    asm volatile(
        "mma.sync.aligned.m16n8k16.row.col.f32.f16.f16.f32 "
        "{%0,%1,%2,%3}, {%4,%5,%6,%7}, {%8,%9}, {%0,%1,%2,%3};\n"
        : "+f"(d[0]), "+f"(d[1]), "+f"(d[2]), "+f"(d[3])
        : "r"(a[0]), "r"(a[1]), "r"(a[2]), "r"(a[3]), "r"(b[0]), "r"(b[1]));
}
__device__ __forceinline__ void ldsm4(uint32_t addr, uint32_t &r0, uint32_t &r1,
                                      uint32_t &r2, uint32_t &r3) {
    asm volatile("ldmatrix.sync.aligned.m8n8.x4.shared.b16 {%0,%1,%2,%3}, [%4];"
                 : "=r"(r0), "=r"(r1), "=r"(r2), "=r"(r3) : "r"(addr));
}
__device__ __forceinline__ void ldsm4t(uint32_t addr, uint32_t &r0, uint32_t &r1,
                                       uint32_t &r2, uint32_t &r3) {
    asm volatile("ldmatrix.sync.aligned.m8n8.x4.trans.shared.b16 {%0,%1,%2,%3}, [%4];"
                 : "=r"(r0), "=r"(r1), "=r"(r2), "=r"(r3) : "r"(addr));
}
__device__ __forceinline__ void cp16(uint32_t saddr, const void* gaddr) {
    asm volatile("cp.async.cg.shared.global [%0], [%1], 16;" :: "r"(saddr), "l"(gaddr));
}
__device__ __forceinline__ void cp4(uint32_t saddr, const void* gaddr) {
    asm volatile("cp.async.ca.shared.global [%0], [%1], 4;" :: "r"(saddr), "l"(gaddr));
}
__device__ __forceinline__ void cp_commit() {
    asm volatile("cp.async.commit_group;" ::: "memory");
}
template <int N>
__device__ __forceinline__ void cp_wait() {
    asm volatile("cp.async.wait_group %0;" :: "n"(N) : "memory");
}
__device__ __forceinline__ uint32_t h2exp2(uint32_t x) {
    uint32_t r;
    asm("ex2.approx.f16x2 %0, %1;" : "=r"(r) : "r"(x));
    return r;
}

// ===========================================================================
// Prep kernels
// ===========================================================================
__global__ __launch_bounds__(256) void cvtX(
    const float* __restrict__ src, __half* __restrict__ dst, int n8)
{
    int i = blockIdx.x * blockDim.x + threadIdx.x;
    if (i < n8) {
        const float4* s4 = (const float4*)src + (size_t)i * 2;
        float4 a = s4[0], b = s4[1];
        __half2 h[4] = { __floats2half2_rn(a.x, a.y), __floats2half2_rn(a.z, a.w),
                         __floats2half2_rn(b.x, b.y), __floats2half2_rn(b.z, b.w) };
        *((uint4*)dst + i) = *(uint4*)h;
    }
}
__global__ __launch_bounds__(256) void cvtW(
    const float* __restrict__ Wq, const float* __restrict__ Wk,
    const float* __restrict__ Wv)
{
    const int z = blockIdx.z;
    const float* src = (z == 0) ? Wq : (z == 1) ? Wk : Wv;
    __half* dst = g_W16 + (size_t)z * H_ * H_;
    int i = blockIdx.x * blockDim.x + threadIdx.x;
    const float4* s4 = (const float4*)src + (size_t)i * 2;
    float4 a = s4[0], b = s4[1];
    __half2 h[4] = { __floats2half2_rn(a.x, a.y), __floats2half2_rn(a.z, a.w),
                     __floats2half2_rn(b.x, b.y), __floats2half2_rn(b.z, b.w) };
    *((uint4*)dst + i) = *(uint4*)h;
}
__global__ __launch_bounds__(256) void prepMask(const float* __restrict__ m)
{
    int i = blockIdx.x * blockDim.x + threadIdx.x;
    g_ML[i] = m[i] * LOG2E;
}

// ===========================================================================
// QKV GEMM — R11-exact (measured 181.8us): 128x128 tiles, 8 warps (4m x 2n),
// warp 32x64, K-chunks of 64, 3-slot cp.async, single barrier per iteration.
// ===========================================================================
#define GLD    72
#define GSTG   (128 * GLD)
#define NSTG   3
#define NCHUNK 16
#define GEMM_SMEM (2 * NSTG * GSTG * 2)    // 110592 bytes

__global__ __launch_bounds__(256, 2) void qkv_gemm_fp16(
    const float* __restrict__ bq, const float* __restrict__ bk,
    const float* __restrict__ bv)
{
    extern __shared__ __align__(16) __half smh[];
    const uint32_t sb = (uint32_t)__cvta_generic_to_shared(smh);

    const int z = blockIdx.z;
    const __half* Wp  = g_W16 + (size_t)z * H_ * H_;
    const float* bias = (z == 0) ? bq : (z == 1) ? bk : bv;
    __half* out       = (z == 0) ? g_Q : (z == 1) ? g_K : g_V;
    const float scale = (z == 0) ? 0.125f * LOG2E : 1.0f;

    const int tid  = threadIdx.x;
    const int lane = tid & 31;
    const int wid  = tid >> 5;
    const int bm   = blockIdx.y * 128;
    const int bn   = blockIdx.x * 128;
    const int moff = (wid & 3) * 32;
    const int noff = (wid >> 2) * 64;
    const int g    = lane >> 2;
    const int c    = lane & 3;
    const int arow = ((lane >> 3) & 1) * 8 + (lane & 7);
    const int acol = (lane >> 4) * 8;
    const int brow = ((lane >> 4) << 3) + (lane & 7);
    const int bcol = ((lane >> 3) & 1) * 8;

    float d[2][8][4];
    #pragma unroll
    for (int mt = 0; mt < 2; mt++)
        #pragma unroll
        for (int nt = 0; nt < 8; nt++)
            #pragma unroll
            for (int e = 0; e < 4; e++) d[mt][nt][e] = 0.f;

    auto issue = [&](int kc, int s) {
        const int k0 = kc * 64;
        #pragma unroll
        for (int i = 0; i < 4; i++) {
            int u = tid + 256 * i;
            int row = u >> 3, c8 = u & 7;
            cp16(sb + (s * GSTG + row * GLD + c8 * 8) * 2,
                 g_X16 + (size_t)(bm + row) * H_ + k0 + c8 * 8);
            cp16(sb + ((NSTG + s) * GSTG + row * GLD + c8 * 8) * 2,
                 Wp + (size_t)(bn + row) * H_ + k0 + c8 * 8);
        }
        cp_commit();
    };

    issue(0, 0);
    issue(1, 1);

    for (int kc = 0; kc < NCHUNK; kc++) {
        const int s = kc % NSTG;
        if (kc == NCHUNK - 1) cp_wait<0>(); else cp_wait<1>();
        __syncthreads();
        if (kc + 2 < NCHUNK) issue(kc + 2, (kc + 2) % NSTG);

        const uint32_t ab = sb + (s * GSTG) * 2;
        const uint32_t bb = sb + ((NSTG + s) * GSTG) * 2;
        #pragma unroll
        for (int kcc = 0; kcc < 4; kcc++) {
            const int kk = kcc * 16;
            uint32_t a[2][4];
            #pragma unroll
            for (int mt = 0; mt < 2; mt++) {
                int row = moff + mt * 16 + arow;
                ldsm4(ab + (row * GLD + kk + acol) * 2,
                      a[mt][0], a[mt][1], a[mt][2], a[mt][3]);
            }
            #pragma unroll
            for (int np = 0; np < 4; np++) {
                uint32_t b0, b1, b2, b3;
                int row = noff + np * 16 + brow;
                ldsm4(bb + (row * GLD + kk + bcol) * 2, b0, b1, b2, b3);
                uint32_t bl[2] = { b0, b1 }, bh[2] = { b2, b3 };
                #pragma unroll
                for (int mt = 0; mt < 2; mt++) {
                    mma_f16(d[mt][2 * np],     a[mt], bl);
                    mma_f16(d[mt][2 * np + 1], a[mt], bh);
                }
            }
        }
    }

    #pragma unroll
    for (int mt = 0; mt < 2; mt++) {
        int row = bm + moff + mt * 16 + g;
        #pragma unroll
        for (int nt = 0; nt < 8; nt++) {
            int col = bn + noff + nt * 8 + 2 * c;
            float2 bv2 = *(const float2*)(bias + col);
            __half2 lo = __floats2half2_rn((d[mt][nt][0] + bv2.x) * scale,
                                           (d[mt][nt][1] + bv2.y) * scale);
            __half2 hi = __floats2half2_rn((d[mt][nt][2] + bv2.x) * scale,
                                           (d[mt][nt][3] + bv2.y) * scale);
            *(__half2*)(out + (size_t)row * H_ + col)       = lo;
            *(__half2*)(out + (size_t)(row + 8) * H_ + col) = hi;
        }
    }
}

// ===========================================================================
// Flash attention — R11 geometry (64-row Q tile, 128 thr, 4 warps x 16 rows,
// single-barrier double-buffered cp.async) with issue-diet softmax:
//  - l via ones-column MMA (no shuffles/scalar adds; denominator uses the
//    same fp16 P as the numerator)
//  - P = ex2.approx.f16x2 (1 MUFU per pair, no separate pack)
//  - skip O/l rescale when no lane raises its running max (cr == 1 exactly)
// ===========================================================================
#define LQH 72

__global__ __launch_bounds__(128) void attn_fp16(float* __restrict__ out)
{
    __shared__ __align__(16) __half Qs[64 * LQH];
    __shared__ __align__(16) __half Ks[2][64 * LQH];
    __shared__ __align__(16) __half Vs[2][64 * LQH];
    __shared__ float Ms[2][64];

    const int tid  = threadIdx.x;
    const int lane = tid & 31;
    const int wid  = tid >> 5;
    const int qb   = (T_ / 64 - 1) - blockIdx.x;   // reversed: heavy first
    const int h    = blockIdx.y;
    const int b    = blockIdx.z;
    const int g    = lane >> 2;
    const int c    = lane & 3;
    const int qrow0 = qb * 64 + wid * 16 + g;

    const uint32_t qs_base = (uint32_t)__cvta_generic_to_shared(Qs);
    const uint32_t ks_base = (uint32_t)__cvta_generic_to_shared(&Ks[0][0]);
    const uint32_t vs_base = (uint32_t)__cvta_generic_to_shared(&Vs[0][0]);
    const uint32_t ms_base = (uint32_t)__cvta_generic_to_shared(&Ms[0][0]);
    const int arow = ((lane >> 3) & 1) * 8 + (lane & 7);
    const int acol = (lane >> 4) * 8;
    const int brow = ((lane >> 4) << 3) + (lane & 7);
    const int bcol = ((lane >> 3) & 1) * 8;

    const size_t hdoff = (size_t)(b * T_) * H_ + h * HD_;
    const __half* kgb = g_K + hdoff;
    const __half* vgb = g_V + hdoff;

    auto issue = [&](int kb, int buf) {
        const __half* kg = kgb + (size_t)kb * 64 * H_;
        const __half* vg = vgb + (size_t)kb * 64 * H_;
        const uint32_t koff = ks_base + buf * (64 * LQH * 2);
        const uint32_t voff = vs_base + buf * (64 * LQH * 2);
        #pragma unroll
        for (int i = 0; i < 4; i++) {
            int u = tid + 128 * i;
            int row = u >> 3, c8 = u & 7;
            cp16(koff + (row * LQH + c8 * 8) * 2, kg + (size_t)row * H_ + c8 * 8);
            cp16(voff + (row * LQH + c8 * 8) * 2, vg + (size_t)row * H_ + c8 * 8);
        }
        if (tid < 64)
            cp4(ms_base + (buf * 64 + tid) * 4, g_ML + (size_t)b * T_ + kb * 64 + tid);
        cp_commit();
    };

    const __half* qg = g_Q + hdoff + (size_t)qb * 64 * H_;
    issue(0, 0);
    #pragma unroll
    for (int i = 0; i < 4; i++) {
        int idx = tid + 128 * i;
        int row = idx >> 3, c8 = idx & 7;
        *(uint4*)&Qs[row * LQH + c8 * 8] =
            *(const uint4*)(qg + (size_t)row * H_ + c8 * 8);
    }
    __syncthreads();

    uint32_t qa[4][4];
    #pragma unroll
    for (int kc = 0; kc < 4; kc++)
        ldsm4(qs_base + ((wid * 16 + arow) * LQH + kc * 16 + acol) * 2,
              qa[kc][0], qa[kc][1], qa[kc][2], qa[kc][3]);

    float o[8][4];
    #pragma unroll
    for (int nt = 0; nt < 8; nt++)
        #pragma unroll
        for (int e = 0; e < 4; e++) o[nt][e] = 0.f;
    float lacc[4] = { 0.f, 0.f, 0.f, 0.f };
    float m0 = -1e30f, m1 = -1e30f;
    const uint32_t onesb[2] = { ONES2, ONES2 };

    for (int kb = 0; kb <= qb; kb++) {
        const int buf = kb & 1;
        cp_wait<0>();
        __syncthreads();
        if (kb < qb) issue(kb + 1, buf ^ 1);

        const uint32_t kbb = ks_base + buf * (64 * LQH * 2);
        const uint32_t vbb = vs_base + buf * (64 * LQH * 2);
        const float* MsB = Ms[buf];

        // ---- S = Q K^T ----
        float s[8][4];
        #pragma unroll
        for (int nt = 0; nt < 8; nt++)
            #pragma unroll
            for (int e = 0; e < 4; e++) s[nt][e] = 0.f;

        #pragma unroll
        for (int kc = 0; kc < 4; kc++) {
            const int kk = kc * 16;
            #pragma unroll
            for (int np = 0; np < 4; np++) {
                uint32_t b0, b1, b2, b3;
                ldsm4(kbb + ((np * 16 + brow) * LQH + kk + bcol) * 2, b0, b1, b2, b3);
                uint32_t bl[2] = { b0, b1 }, bh[2] = { b2, b3 };
                mma_f16(s[2 * np],     qa[kc], bl);
                mma_f16(s[2 * np + 1], qa[kc], bh);
            }
        }

        // ---- mask + online softmax (exp2 domain) ----
        float rmax0 = -1e30f, rmax1 = -1e30f;
        #pragma unroll
        for (int nt = 0; nt < 8; nt++) {
            int lc = nt * 8 + 2 * c;
            float mk0 = MsB[lc], mk1 = MsB[lc + 1];
            s[nt][0] += mk0; s[nt][1] += mk1;
            s[nt][2] += mk0; s[nt][3] += mk1;
            if (kb == qb) {
                int col = kb * 64 + lc;
                if (col     > qrow0)     s[nt][0] = -1e30f;
                if (col + 1 > qrow0)     s[nt][1] = -1e30f;
                if (col     > qrow0 + 8) s[nt][2] = -1e30f;
                if (col + 1 > qrow0 + 8) s[nt][3] = -1e30f;
            }
            rmax0 = fmaxf(rmax0, fmaxf(s[nt][0], s[nt][1]));
            rmax1 = fmaxf(rmax1, fmaxf(s[nt][2], s[nt][3]));
        }
        rmax0 = fmaxf(rmax0, __shfl_xor_sync(0xffffffffu, rmax0, 1));
        rmax0 = fmaxf(rmax0, __shfl_xor_sync(0xffffffffu, rmax0, 2));
        rmax1 = fmaxf(rmax1, __shfl_xor_sync(0xffffffffu, rmax1, 1));
        rmax1 = fmaxf(rmax1, __shfl_xor_sync(0xffffffffu, rmax1, 2));

        float mn0 = fmaxf(m0, rmax0), mn1 = fmaxf(m1, rmax1);
        if (__any_sync(0xffffffffu, (mn0 > m0) | (mn1 > m1))) {
            float cr0 = exp2f(m0 - mn0), cr1 = exp2f(m1 - mn1);
            #pragma unroll
            for (int nt = 0; nt < 8; nt++) {
                o[nt][0] *= cr0; o[nt][1] *= cr0;
                o[nt][2] *= cr1; o[nt][3] *= cr1;
            }
            lacc[0] *= cr0; lacc[2] *= cr1;
            m0 = mn0; m1 = mn1;
        }

        // ---- P = 2^(s-m) directly in fp16 pairs ----
        uint32_t ph[8][2];
        #pragma unroll
        for (int nt = 0; nt < 8; nt++) {
            __half2 t01 = __floats2half2_rn(s[nt][0] - m0, s[nt][1] - m0);
            __half2 t23 = __floats2half2_rn(s[nt][2] - m1, s[nt][3] - m1);
            ph[nt][0] = h2exp2(*(uint32_t*)&t01);
            ph[nt][1] = h2exp2(*(uint32_t*)&t23);
        }

        // ---- O += P V ; l += P * ones ----
        #pragma unroll
        for (int jc = 0; jc < 4; jc++) {
            uint32_t a[4] = { ph[2 * jc][0], ph[2 * jc][1],
                              ph[2 * jc + 1][0], ph[2 * jc + 1][1] };
            mma_f16(lacc, a, onesb);
            #pragma unroll
            for (int dp = 0; dp < 4; dp++) {
                uint32_t b0, b1, b2, b3;
                ldsm4t(vbb + ((jc * 16 + arow) * LQH + dp * 16 + acol) * 2,
                       b0, b1, b2, b3);
                uint32_t bl[2] = { b0, b1 }, bh[2] = { b2, b3 };
                mma_f16(o[2 * dp],     a, bl);
                mma_f16(o[2 * dp + 1], a, bh);
            }
        }
    }

    float inv0 = 1.f / lacc[0], inv1 = 1.f / lacc[2];
    float* og = out + ((size_t)(b * T_) + (size_t)qb * 64 + wid * 16 + g) * H_ + h * HD_;
    #pragma unroll
    for (int nt = 0; nt < 8; nt++) {
        int lc = nt * 8 + 2 * c;
        float2 w0, w1;
        w0.x = o[nt][0] * inv0; w0.y = o[nt][1] * inv0;
        w1.x = o[nt][2] * inv1; w1.y = o[nt][3] * inv1;
        *(float2*)(og + lc)          = w0;
        *(float2*)(og + 8 * H_ + lc) = w1;
    }
}

// ===========================================================================
// Launch
// ===========================================================================
extern "C" void kernel_launch(void* const* d_in, const int* in_sizes, int n_in,
                              void* d_out, int out_size)
{
    const float* x    = (const float*)d_in[0];
    const float* mask = (const float*)d_in[1];
    const float* Wq   = (const float*)d_in[2];
    const float* bq   = (const float*)d_in[3];
    const float* Wk   = (const float*)d_in[4];
    const float* bk   = (const float*)d_in[5];
    const float* Wv   = (const float*)d_in[6];
    const float* bv   = (const float*)d_in[7];
    float* out = (float*)d_out;

    __half *X16p;
    cudaGetSymbolAddress((void**)&X16p, g_X16);

    cudaFuncSetAttribute(qkv_gemm_fp16, cudaFuncAttributeMaxDynamicSharedMemorySize,
                         GEMM_SMEM);

    cvtX<<<(M_ * H_ / 8 + 255) / 256, 256>>>(x, X16p, M_ * H_ / 8);
    dim3 wgrid(H_ * H_ / 8 / 256, 1, 3);
    cvtW<<<wgrid, 256>>>(Wq, Wk, Wv);
    prepMask<<<B_ * T_ / 256, 256>>>(mask);

    dim3 ggrid(H_ / 128, M_ / 128, 3);   // (8, 64, 3)
    qkv_gemm_fp16<<<ggrid, 256, GEMM_SMEM>>>(bq, bk, bv);

    dim3 agrid(T_ / 64, NH_, B_);        // (32, 16, 4)
    attn_fp16<<<agrid, 128>>>(out);
}